// round 12
// baseline (speedup 1.0000x reference)
#include <cuda_runtime.h>
#include <cstdint>

// Problem constants
#define Bn 4
#define Cn 32
#define Ln 256
#define Mn 256
#define Fn 8
#define Nn 64
#define FC (Fn * Cn)          // 256
#define LM (Ln * Mn)          // 65536
#define IMAG_OFF ((size_t)Bn * Fn * LM)  // 2,097,152

#define NSTAGE 3
#define CPS 4                 // c per stage
#define NROUND (Cn / CPS)     // 8
#define STAGE_B (CPS * 2 * Mn * 4)   // 8192

union U64 {
    unsigned long long u;
    float2 f;
};

__device__ __forceinline__ unsigned long long ffma2(unsigned long long a,
                                                    unsigned long long b,
                                                    unsigned long long c) {
    unsigned long long d;
    asm("fma.rn.f32x2 %0, %1, %2, %3;" : "=l"(d) : "l"(a), "l"(b), "l"(c));
    return d;
}

__device__ __forceinline__ uint32_t smem_u32(const void* p) {
    uint32_t a;
    asm("{ .reg .u64 t; cvta.to.shared.u64 t, %1; cvt.u32.u64 %0, t; }"
        : "=r"(a) : "l"(p));
    return a;
}

__device__ __forceinline__ void cp16(uint32_t smem, const void* gmem) {
    asm volatile("cp.async.cg.shared.global [%0], [%1], 16;"
                 :: "r"(smem), "l"(gmem));
}
__device__ __forceinline__ void cp_commit() {
    asm volatile("cp.async.commit_group;");
}
template <int N>
__device__ __forceinline__ void cp_wait() {
    asm volatile("cp.async.wait_group %0;" :: "n"(N));
}

__device__ __forceinline__ void mbar_init(uint32_t bar, uint32_t count) {
    asm volatile("mbarrier.init.shared.b64 [%0], %1;" :: "r"(bar), "r"(count)
                 : "memory");
}
__device__ __forceinline__ void mbar_arrive(uint32_t bar) {
    asm volatile("mbarrier.arrive.release.cta.shared::cta.b64 _, [%0];"
                 :: "r"(bar) : "memory");
}
__device__ __forceinline__ void mbar_wait(uint32_t bar, uint32_t parity) {
    asm volatile(
        "{\n\t"
        ".reg .pred P;\n\t"
        "WAIT_%=:\n\t"
        "mbarrier.try_wait.parity.acquire.cta.shared::cta.b64 P, [%0], %1, 0x989680;\n\t"
        "@P bra DONE_%=;\n\t"
        "bra WAIT_%=;\n\t"
        "DONE_%=:\n\t"
        "}"
        :: "r"(bar), "r"(parity) : "memory");
}

// ---------------------------------------------------------------------------
// Warp-specialized: grid = B*L = 1024 blocks, 160 threads.
// Warp 0 = producer (cp.async x into 3-stage x 8KB ring, always loading).
// Warps 1-4 = consumers (128 threads, 2 m each, all 8 f, FFMA from shared).
// __launch_bounds__(160, 7): 7 blocks/SM -> single wave of 1024.
// ---------------------------------------------------------------------------
__global__ __launch_bounds__(160, 7) void sphere_ws_kernel(
    const float* __restrict__ xr,
    const float* __restrict__ xi,
    const float* __restrict__ wr,
    const float* __restrict__ wi,
    float* __restrict__ out) {
    __shared__ ulonglong2 s2[FC];                       // 4 KB weights
    __shared__ __align__(16) char ring[NSTAGE * STAGE_B]; // 24 KB x ring
    __shared__ __align__(8) unsigned long long barF[NSTAGE], barE[NSTAGE];

    int tid = threadIdx.x;
    int bid = blockIdx.x;
    int b = bid >> 8;
    int l = bid & (Ln - 1);

    // --- interpolate this l's weights into shared (threads 0-127) ---
    if (tid < 128) {
        float t = (float)l * (63.0f / 255.0f);
        int lo = (int)t;
        if (lo > Nn - 2) lo = Nn - 2;
        float fr = t - (float)lo;
        float om = 1.0f - fr;
#pragma unroll
        for (int j = 0; j < 2; ++j) {
            int k = tid + j * 128;
            const float* pwr = wr + k * Nn + lo;
            const float* pwi = wi + k * Nn + lo;
            float vr = pwr[0] * om + pwr[1] * fr;
            float vi = pwi[0] * om + pwi[1] * fr;
            U64 ur, ui;
            ur.f = make_float2(vr, vr);
            ui.f = make_float2(vi, vi);
            s2[k] = make_ulonglong2(ur.u, ui.u);
        }
    }
    if (tid == 0) {
#pragma unroll
        for (int s = 0; s < NSTAGE; ++s) {
            mbar_init(smem_u32(&barF[s]), 1);    // producer lane0 arrives
            mbar_init(smem_u32(&barE[s]), 4);    // 4 consumer warps arrive
        }
    }
    __syncthreads();

    uint32_t fb = smem_u32(barF);
    uint32_t eb = smem_u32(barE);

    if (tid < 32) {
        // ================= PRODUCER WARP =================
        int lane = tid;
        const char* gr = reinterpret_cast<const char*>(xr) +
                         ((size_t)b * Cn * LM + (size_t)l * Mn) * 4;
        const char* gi = reinterpret_cast<const char*>(xi) +
                         ((size_t)b * Cn * LM + (size_t)l * Mn) * 4;
        uint32_t rb = smem_u32(ring);
        int es = 0, ep = 1;     // empty-wait cursor (init phase 1: first pass free)
        int as_ = 0;            // full-arrive stage cursor

        for (int k = 0; k < NROUND; ++k) {
            mbar_wait(eb + es * 8, ep);
            uint32_t sb = rb + es * STAGE_B + lane * 16;
#pragma unroll
            for (int j = 0; j < CPS; ++j) {
                size_t cb = (size_t)(k * CPS + j) * ((size_t)LM * 4);
                uint32_t d = sb + j * 2048;
                cp16(d,        gr + cb + lane * 16);
                cp16(d + 512,  gr + cb + lane * 16 + 512);
                cp16(d + 1024, gi + cb + lane * 16);
                cp16(d + 1536, gi + cb + lane * 16 + 512);
            }
            cp_commit();
            if (k >= 2) {
                cp_wait<2>();
                if (lane == 0) mbar_arrive(fb + as_ * 8);
                if (++as_ == NSTAGE) as_ = 0;
            }
            if (++es == NSTAGE) { es = 0; ep ^= 1; }
        }
        // drain: rounds NROUND-2, NROUND-1
        cp_wait<1>();
        if (lane == 0) mbar_arrive(fb + as_ * 8);
        if (++as_ == NSTAGE) as_ = 0;
        cp_wait<0>();
        if (lane == 0) mbar_arrive(fb + as_ * 8);
    } else {
        // ================= CONSUMER WARPS =================
        int ct = tid - 32;      // 0..127
        const unsigned long long* r64 =
            reinterpret_cast<const unsigned long long*>(ring);

        unsigned long long ar[Fn], ai[Fn];
#pragma unroll
        for (int f = 0; f < Fn; ++f) { ar[f] = 0ull; ai[f] = 0ull; }

        const unsigned long long SMSK = 0x8000000080000000ULL;
        int cs = 0, cph = 0;

        for (int k = 0; k < NROUND; ++k) {
            mbar_wait(fb + cs * 8, cph);
            int xb = cs * (STAGE_B / 8) + ct;
#pragma unroll
            for (int j = 0; j < CPS; ++j) {
                unsigned long long xrc = r64[xb + j * 256];
                unsigned long long xic = r64[xb + j * 256 + 128];
                unsigned long long nxi = xic ^ SMSK;
                int c = k * CPS + j;
#pragma unroll
                for (int f = 0; f < Fn; ++f) {
                    ulonglong2 w = s2[f * Cn + c];   // broadcast LDS.128
                    ar[f] = ffma2(w.x, xrc, ar[f]);
                    ar[f] = ffma2(w.y, nxi, ar[f]);
                    ai[f] = ffma2(w.x, xic, ai[f]);
                    ai[f] = ffma2(w.y, xrc, ai[f]);
                }
            }
            if ((tid & 31) == 0) mbar_arrive(eb + cs * 8);
            if (++cs == NSTAGE) { cs = 0; cph ^= 1; }
        }

        float sc = sqrtf(1.0f + (float)l) * (1.0f / 32.0f);
        int m0 = ct * 2;
        float* o_real = out + (size_t)b * Fn * LM + (size_t)l * Mn + m0;
        float* o_imag = o_real + IMAG_OFF;

#pragma unroll
        for (int f = 0; f < Fn; ++f) {
            U64 u;
            u.u = ar[f];
            float2 vr2;
            vr2.x = fmaxf(u.f.x * sc, 0.0f);
            vr2.y = fmaxf(u.f.y * sc, 0.0f);
            *reinterpret_cast<float2*>(o_real + (size_t)f * LM) = vr2;

            u.u = ai[f];
            float2 vi2;
            vi2.x = u.f.x * sc;
            vi2.y = u.f.y * sc;
            *reinterpret_cast<float2*>(o_imag + (size_t)f * LM) = vi2;
        }
    }
}

extern "C" void kernel_launch(void* const* d_in, const int* in_sizes, int n_in,
                              void* d_out, int out_size) {
    const float* x_real = (const float*)d_in[0];
    const float* x_imag = (const float*)d_in[1];
    const float* w_real = (const float*)d_in[2];
    const float* w_imag = (const float*)d_in[3];
    float* out = (float*)d_out;

    sphere_ws_kernel<<<Bn * Ln, 160>>>(x_real, x_imag, w_real, w_imag, out);
}

// round 13
// speedup vs baseline: 1.0816x; 1.0816x over previous
#include <cuda_runtime.h>
#include <cstdint>

// Problem constants
#define Bn 4
#define Cn 32
#define Ln 256
#define Mn 256
#define Fn 8
#define Nn 64
#define FC (Fn * Cn)          // 256
#define LM (Ln * Mn)          // 65536
#define IMAG_OFF ((size_t)Bn * Fn * LM)  // 2,097,152
#define CB 8                  // c-batch size (front-batched loads)

union U64 {
    unsigned long long u;
    float2 f;
};

__device__ __forceinline__ unsigned long long ffma2(unsigned long long a,
                                                    unsigned long long b,
                                                    unsigned long long c) {
    unsigned long long d;
    asm("fma.rn.f32x2 %0, %1, %2, %3;" : "=l"(d) : "l"(a), "l"(b), "l"(c));
    return d;
}

// ---------------------------------------------------------------------------
// Grid: B*L = 1024 blocks, 128 threads. Block = one (b, l).
// Thread t: m-pair t (2 consecutive m), all 8 f.
// Key changes vs R7:
//  - batch 0's 16 x-loads issue BEFORE weight interp (startup overlap)
//  - __ldcs streaming loads (x lines are single-use chip-wide)
//  - __launch_bounds__(128, 7): 7 blocks/SM -> single wave of 1036 >= 1024
// ---------------------------------------------------------------------------
__global__ __launch_bounds__(128, 7) void sphere_v13_kernel(
    const float* __restrict__ xr,
    const float* __restrict__ xi,
    const float* __restrict__ wr,
    const float* __restrict__ wi,
    float* __restrict__ out) {
    __shared__ ulonglong2 s2[FC];   // 4 KB: { {wr,wr}, {wi,wi} } per (f,c)

    int bid = blockIdx.x;
    int b = bid >> 8;
    int l = bid & (Ln - 1);
    int tid = threadIdx.x;

    int m0 = tid * 2;
    const unsigned long long* pr = reinterpret_cast<const unsigned long long*>(
        xr + (size_t)b * Cn * LM + (size_t)l * Mn + m0);
    const unsigned long long* pi = reinterpret_cast<const unsigned long long*>(
        xi + (size_t)b * Cn * LM + (size_t)l * Mn + m0);
    const int step = LM / 2;   // u64 stride per c (byte offset fits imm24)

    // ---- issue batch 0's x loads FIRST (overlap with weight interp) ----
    unsigned long long xrv[CB], xiv[CB];
#pragma unroll
    for (int j = 0; j < CB; ++j) {
        xrv[j] = __ldcs(pr + j * step);
        xiv[j] = __ldcs(pi + j * step);
    }
    pr += CB * step;
    pi += CB * step;

    // --- interpolate this l's weights into shared (covered by x latency) ---
    {
        float t = (float)l * (63.0f / 255.0f);
        int lo = (int)t;
        if (lo > Nn - 2) lo = Nn - 2;
        float fr = t - (float)lo;
        float om = 1.0f - fr;
#pragma unroll
        for (int j = 0; j < 2; ++j) {
            int k = tid + j * 128;
            const float* pwr = wr + k * Nn + lo;
            const float* pwi = wi + k * Nn + lo;
            float vr = pwr[0] * om + pwr[1] * fr;
            float vi = pwi[0] * om + pwi[1] * fr;
            U64 ur, ui;
            ur.f = make_float2(vr, vr);
            ui.f = make_float2(vi, vi);
            s2[k] = make_ulonglong2(ur.u, ui.u);
        }
    }
    __syncthreads();

    unsigned long long ar[Fn], ai[Fn];
#pragma unroll
    for (int f = 0; f < Fn; ++f) { ar[f] = 0ull; ai[f] = 0ull; }

    const unsigned long long SMSK = 0x8000000080000000ULL;

#pragma unroll
    for (int cb = 0; cb < Cn; cb += CB) {
        // ---- compute current batch ----
#pragma unroll
        for (int j = 0; j < CB; ++j) {
            int c = cb + j;
            unsigned long long xrc = xrv[j];
            unsigned long long xic = xiv[j];
            unsigned long long nxi = xic ^ SMSK;
#pragma unroll
            for (int f = 0; f < Fn; ++f) {
                ulonglong2 w = s2[f * Cn + c];   // broadcast LDS.128
                ar[f] = ffma2(w.x, xrc, ar[f]);
                ar[f] = ffma2(w.y, nxi, ar[f]);
                ai[f] = ffma2(w.x, xic, ai[f]);
                ai[f] = ffma2(w.y, xrc, ai[f]);
            }
            // refill this slot with the next batch's value right after use:
            // single-buffer software pipeline, no extra registers.
            if (cb + CB < Cn) {
                xrv[j] = __ldcs(pr + j * step);
                xiv[j] = __ldcs(pi + j * step);
            }
        }
        pr += CB * step;
        pi += CB * step;
    }

    float sc = sqrtf(1.0f + (float)l) * (1.0f / 32.0f);
    float* o_real = out + (size_t)b * Fn * LM + (size_t)l * Mn + m0;
    float* o_imag = o_real + IMAG_OFF;

#pragma unroll
    for (int f = 0; f < Fn; ++f) {
        U64 u;
        u.u = ar[f];
        float2 vr2;
        vr2.x = fmaxf(u.f.x * sc, 0.0f);
        vr2.y = fmaxf(u.f.y * sc, 0.0f);
        __stcs(reinterpret_cast<float2*>(o_real + (size_t)f * LM), vr2);

        u.u = ai[f];
        float2 vi2;
        vi2.x = u.f.x * sc;
        vi2.y = u.f.y * sc;
        __stcs(reinterpret_cast<float2*>(o_imag + (size_t)f * LM), vi2);
    }
}

extern "C" void kernel_launch(void* const* d_in, const int* in_sizes, int n_in,
                              void* d_out, int out_size) {
    const float* x_real = (const float*)d_in[0];
    const float* x_imag = (const float*)d_in[1];
    const float* w_real = (const float*)d_in[2];
    const float* w_imag = (const float*)d_in[3];
    float* out = (float*)d_out;

    sphere_v13_kernel<<<Bn * Ln, 128>>>(x_real, x_imag, w_real, w_imag, out);
}

// round 14
// speedup vs baseline: 1.2947x; 1.1969x over previous
#include <cuda_runtime.h>
#include <cstdint>

// Problem constants
#define Bn 4
#define Cn 32
#define Ln 256
#define Mn 256
#define Fn 8
#define Nn 64
#define FC (Fn * Cn)          // 256
#define LM (Ln * Mn)          // 65536
#define IMAG_OFF ((size_t)Bn * Fn * LM)  // 2,097,152
#define CB 8                  // c-batch size (front-batched loads)

union U64 {
    unsigned long long u;
    float2 f;
};

__device__ __forceinline__ unsigned long long ffma2(unsigned long long a,
                                                    unsigned long long b,
                                                    unsigned long long c) {
    unsigned long long d;
    asm("fma.rn.f32x2 %0, %1, %2, %3;" : "=l"(d) : "l"(a), "l"(b), "l"(c));
    return d;
}

// ---------------------------------------------------------------------------
// Grid: 2 * L = 512 blocks, 256 threads. Block = (b-pair, l).
// Threads 0-127 -> b = bp*2, threads 128-255 -> b = bp*2+1 (same l, shared
// weights). Each thread: m-pair (2 consecutive m), all 8 f.
// Batch-0 x loads issue BEFORE weight interp (startup overlap).
// Mainloop identical to the 21.0us champion (CB=8 front-batch, __ldg).
// ---------------------------------------------------------------------------
__global__ __launch_bounds__(256, 3) void sphere_v14_kernel(
    const float* __restrict__ xr,
    const float* __restrict__ xi,
    const float* __restrict__ wr,
    const float* __restrict__ wi,
    float* __restrict__ out) {
    __shared__ ulonglong2 s2[FC];   // 4 KB: { {wr,wr}, {wi,wi} } per (f,c)

    int bid = blockIdx.x;
    int bp = bid >> 8;              // b-pair: 0 -> b{0,1}, 1 -> b{2,3}
    int l = bid & (Ln - 1);
    int tid = threadIdx.x;

    int b = bp * 2 + (tid >> 7);    // per-half b
    int m0 = (tid & 127) * 2;

    const unsigned long long* pr = reinterpret_cast<const unsigned long long*>(
        xr + (size_t)b * Cn * LM + (size_t)l * Mn + m0);
    const unsigned long long* pi = reinterpret_cast<const unsigned long long*>(
        xi + (size_t)b * Cn * LM + (size_t)l * Mn + m0);
    const int step = LM / 2;        // u64 stride per c (byte offset fits imm24)

    // ---- issue batch 0's x loads FIRST (overlap with weight interp) ----
    unsigned long long xrv[CB], xiv[CB];
#pragma unroll
    for (int j = 0; j < CB; ++j) {
        xrv[j] = __ldg(pr + j * step);
        xiv[j] = __ldg(pi + j * step);
    }
    pr += CB * step;
    pi += CB * step;

    // --- interpolate this l's weights into shared (1 entry per thread) ---
    {
        float t = (float)l * (63.0f / 255.0f);
        int lo = (int)t;
        if (lo > Nn - 2) lo = Nn - 2;
        float fr = t - (float)lo;
        float om = 1.0f - fr;
        int k = tid;                 // covers FC = 256 exactly
        const float* pwr = wr + k * Nn + lo;
        const float* pwi = wi + k * Nn + lo;
        float vr = pwr[0] * om + pwr[1] * fr;
        float vi = pwi[0] * om + pwi[1] * fr;
        U64 ur, ui;
        ur.f = make_float2(vr, vr);
        ui.f = make_float2(vi, vi);
        s2[k] = make_ulonglong2(ur.u, ui.u);
    }
    __syncthreads();

    unsigned long long ar[Fn], ai[Fn];
#pragma unroll
    for (int f = 0; f < Fn; ++f) { ar[f] = 0ull; ai[f] = 0ull; }

    const unsigned long long SMSK = 0x8000000080000000ULL;

#pragma unroll
    for (int cb = 0; cb < Cn; cb += CB) {
        // ---- compute current batch ----
#pragma unroll
        for (int j = 0; j < CB; ++j) {
            int c = cb + j;
            unsigned long long xrc = xrv[j];
            unsigned long long xic = xiv[j];
            unsigned long long nxi = xic ^ SMSK;
#pragma unroll
            for (int f = 0; f < Fn; ++f) {
                ulonglong2 w = s2[f * Cn + c];   // broadcast LDS.128
                ar[f] = ffma2(w.x, xrc, ar[f]);
                ar[f] = ffma2(w.y, nxi, ar[f]);
                ai[f] = ffma2(w.x, xic, ai[f]);
                ai[f] = ffma2(w.y, xrc, ai[f]);
            }
        }
        // ---- front-batched loads for next batch (R7 style: all at once) ----
        if (cb + CB < Cn) {
#pragma unroll
            for (int j = 0; j < CB; ++j) {
                xrv[j] = __ldg(pr + j * step);
                xiv[j] = __ldg(pi + j * step);
            }
            pr += CB * step;
            pi += CB * step;
        }
    }

    float sc = sqrtf(1.0f + (float)l) * (1.0f / 32.0f);
    float* o_real = out + (size_t)b * Fn * LM + (size_t)l * Mn + m0;
    float* o_imag = o_real + IMAG_OFF;

#pragma unroll
    for (int f = 0; f < Fn; ++f) {
        U64 u;
        u.u = ar[f];
        float2 vr2;
        vr2.x = fmaxf(u.f.x * sc, 0.0f);
        vr2.y = fmaxf(u.f.y * sc, 0.0f);
        *reinterpret_cast<float2*>(o_real + (size_t)f * LM) = vr2;

        u.u = ai[f];
        float2 vi2;
        vi2.x = u.f.x * sc;
        vi2.y = u.f.y * sc;
        *reinterpret_cast<float2*>(o_imag + (size_t)f * LM) = vi2;
    }
}

extern "C" void kernel_launch(void* const* d_in, const int* in_sizes, int n_in,
                              void* d_out, int out_size) {
    const float* x_real = (const float*)d_in[0];
    const float* x_imag = (const float*)d_in[1];
    const float* w_real = (const float*)d_in[2];
    const float* w_imag = (const float*)d_in[3];
    float* out = (float*)d_out;

    sphere_v14_kernel<<<2 * Ln, 256>>>(x_real, x_imag, w_real, w_imag, out);
}